// round 9
// baseline (speedup 1.0000x reference)
#include <cuda_runtime.h>
#include <cstdint>

// ---------------- problem constants ----------------
#define N_SRC0 200000
#define N_DST0 50000
#define N_DST1 10000
#define NPAIR  5000
#define FEAT   256
#define NB     4
#define BCAP   64     // Poisson(16); P(deg>64) astronomically small
#define OVFCAP 2048   // spill list for pathological degrees

// ---------------- scratch (static device globals; no runtime alloc) --------
__device__ float g_aggX0[(size_t)N_DST0 * FEAT];  // segment-sum of x rows
__device__ float g_h1[(size_t)N_DST0 * FEAT];
__device__ float g_aggX1[(size_t)N_DST1 * FEAT];
__device__ float g_e[(size_t)(2 * NPAIR) * FEAT];
__device__ float g_hid[(size_t)(2 * NPAIR) * 128];
__device__ int   g_cnt0[N_DST0 + 1];              // last slot = overflow count
__device__ int   g_cnt1[N_DST1 + 1];
__device__ int   g_bk0[(size_t)N_DST0 * BCAP];
__device__ int   g_bk1[(size_t)N_DST1 * BCAP];
__device__ int   g_ovf0[OVFCAP * 2];              // (src,dst) pairs
__device__ int   g_ovf1[OVFCAP * 2];

// ---------------- f32x2 helpers (Blackwell packed FMA) ----------------------
__device__ __forceinline__ unsigned long long fma2(
    unsigned long long a, unsigned long long b, unsigned long long c)
{
    unsigned long long d;
    asm("fma.rn.f32x2 %0, %1, %2, %3;" : "=l"(d) : "l"(a), "l"(b), "l"(c));
    return d;
}
__device__ __forceinline__ unsigned long long dup2(float v)
{
    unsigned u = __float_as_uint(v);
    return (unsigned long long)u | ((unsigned long long)u << 32);
}
__device__ __forceinline__ void unpack2(unsigned long long p, float& lo, float& hi)
{
    lo = __uint_as_float((unsigned)p);
    hi = __uint_as_float((unsigned)(p >> 32));
}

// ---------------------------------------------------------------------------
// Fused relational-layer GEMM:
//   C[:, n0:n0+64] = relu?( A@B[:, n0:n0+64] + AGG[:, b*64:+64] @ Wb + bias )
// b = blockIdx.x (one bdd base per 64-wide n-tile). AGG==nullptr skips fusion.
// Tile: 256 (M) x 64 (N), 256 threads, 16x4 microtile, packed fma.rn.f32x2.
// B staged in smem PRE-DUPLICATED as (v,v) u64 pairs (split arrays: 16B lane
// stride, conflict-free). A fragments are loaded JUST-IN-TIME (short live
// range -> no register spill at the 128-reg / 2-CTA cap); only the 4-reg B
// prefetch pipelines across the compute loop. Exposed A-load latency is
// covered by the co-resident CTA (occ=2) and L2 residency (4 n-tiles reuse
// each A row; grid = (N/64, M/256) with n fastest).
// ---------------------------------------------------------------------------
__global__ __launch_bounds__(256, 2) void gemm_fused(
    const float* __restrict__ A, const float* __restrict__ B,
    const float* __restrict__ AGG, const float* __restrict__ W,
    const float* __restrict__ bias, float* __restrict__ C,
    int M, int N, int doRelu)
{
    __shared__ __align__(16) float As[16][256];                 // 16 KB
    __shared__ __align__(16) unsigned long long Bd0[16][32];    // 4 KB
    __shared__ __align__(16) unsigned long long Bd1[16][32];    // 4 KB

    const int tid = threadIdx.x;
    const int n0 = blockIdx.x * 64;
    const int m0 = blockIdx.y * 256;
    const int b  = blockIdx.x;          // bdd base when AGG active (N==256)

    const int ty = tid >> 4;            // 0..15 -> rows ty*16..+15
    const int tx = tid & 15;            // 0..15 -> cols tx*4..+3
    const int bk = tid >> 4;            // B-stage k row
    const int bt = tid & 15;            // B-stage col group (4 cols)

    unsigned long long acc[8][4];       // [row-pair][col]
#pragma unroll
    for (int p = 0; p < 8; p++)
#pragma unroll
        for (int j = 0; j < 4; j++) acc[p][j] = 0ull;

    const int arow = m0 + tid;          // one A row per thread for staging
    const bool aok = (arow < M);
    const float* Wb = W ? (W + (size_t)b * 64 * 64) : nullptr;
    const int ktot = AGG ? 320 : 256;   // 256 main + 64 fused bdd K-steps

    // B prefetch register (only 4 regs live across the compute loop)
    float4 bv = *(const float4*)(B + (size_t)bk * N + n0 + bt * 4);

    for (int kt = 0; kt < ktot; kt += 16) {
        // ---- stage B from prefetched regs (duplicated pairs) ----
        {
            ulonglong2 d01; d01.x = dup2(bv.x); d01.y = dup2(bv.y);
            ulonglong2 d23; d23.x = dup2(bv.z); d23.y = dup2(bv.w);
            *(ulonglong2*)&Bd0[bk][bt * 2] = d01;
            *(ulonglong2*)&Bd1[bk][bt * 2] = d23;
        }
        // ---- load + stage A just-in-time (short live range, no spill) ----
        {
            float4 v0, v1, v2, v3;
            v0 = v1 = v2 = v3 = make_float4(0.f, 0.f, 0.f, 0.f);
            if (aok) {
                const float* src = (kt < 256)
                    ? (A + (size_t)arow * 256 + kt)
                    : (AGG + (size_t)arow * 256 + b * 64 + (kt - 256));
                v0 = *(const float4*)(src + 0);
                v1 = *(const float4*)(src + 4);
                v2 = *(const float4*)(src + 8);
                v3 = *(const float4*)(src + 12);
            }
            As[ 0][tid] = v0.x; As[ 1][tid] = v0.y; As[ 2][tid] = v0.z; As[ 3][tid] = v0.w;
            As[ 4][tid] = v1.x; As[ 5][tid] = v1.y; As[ 6][tid] = v1.z; As[ 7][tid] = v1.w;
            As[ 8][tid] = v2.x; As[ 9][tid] = v2.y; As[10][tid] = v2.z; As[11][tid] = v2.w;
            As[12][tid] = v3.x; As[13][tid] = v3.y; As[14][tid] = v3.z; As[15][tid] = v3.w;
        }
        __syncthreads();

        // ---- prefetch next B tile (4 regs; latency hidden by compute) ----
        const int kn = kt + 16;
        if (kn < ktot) {
            if (kn < 256)
                bv = *(const float4*)(B + (size_t)(kn + bk) * N + n0 + bt * 4);
            else
                bv = *(const float4*)(Wb + (size_t)(kn - 256 + bk) * 64 + bt * 4);
        }

        // ---- compute 16 k-steps from smem ----
#pragma unroll
        for (int k = 0; k < 16; k++) {
            ulonglong2 b01 = *(const ulonglong2*)&Bd0[k][tx * 2];
            ulonglong2 b23 = *(const ulonglong2*)&Bd1[k][tx * 2];

            ulonglong2 a0 = *(const ulonglong2*)&As[k][ty * 16 + 0];
            acc[0][0] = fma2(a0.x, b01.x, acc[0][0]);
            acc[0][1] = fma2(a0.x, b01.y, acc[0][1]);
            acc[0][2] = fma2(a0.x, b23.x, acc[0][2]);
            acc[0][3] = fma2(a0.x, b23.y, acc[0][3]);
            acc[1][0] = fma2(a0.y, b01.x, acc[1][0]);
            acc[1][1] = fma2(a0.y, b01.y, acc[1][1]);
            acc[1][2] = fma2(a0.y, b23.x, acc[1][2]);
            acc[1][3] = fma2(a0.y, b23.y, acc[1][3]);

            ulonglong2 a1 = *(const ulonglong2*)&As[k][ty * 16 + 4];
            acc[2][0] = fma2(a1.x, b01.x, acc[2][0]);
            acc[2][1] = fma2(a1.x, b01.y, acc[2][1]);
            acc[2][2] = fma2(a1.x, b23.x, acc[2][2]);
            acc[2][3] = fma2(a1.x, b23.y, acc[2][3]);
            acc[3][0] = fma2(a1.y, b01.x, acc[3][0]);
            acc[3][1] = fma2(a1.y, b01.y, acc[3][1]);
            acc[3][2] = fma2(a1.y, b23.x, acc[3][2]);
            acc[3][3] = fma2(a1.y, b23.y, acc[3][3]);

            ulonglong2 a2 = *(const ulonglong2*)&As[k][ty * 16 + 8];
            acc[4][0] = fma2(a2.x, b01.x, acc[4][0]);
            acc[4][1] = fma2(a2.x, b01.y, acc[4][1]);
            acc[4][2] = fma2(a2.x, b23.x, acc[4][2]);
            acc[4][3] = fma2(a2.x, b23.y, acc[4][3]);
            acc[5][0] = fma2(a2.y, b01.x, acc[5][0]);
            acc[5][1] = fma2(a2.y, b01.y, acc[5][1]);
            acc[5][2] = fma2(a2.y, b23.x, acc[5][2]);
            acc[5][3] = fma2(a2.y, b23.y, acc[5][3]);

            ulonglong2 a3 = *(const ulonglong2*)&As[k][ty * 16 + 12];
            acc[6][0] = fma2(a3.x, b01.x, acc[6][0]);
            acc[6][1] = fma2(a3.x, b01.y, acc[6][1]);
            acc[6][2] = fma2(a3.x, b23.x, acc[6][2]);
            acc[6][3] = fma2(a3.x, b23.y, acc[6][3]);
            acc[7][0] = fma2(a3.y, b01.x, acc[7][0]);
            acc[7][1] = fma2(a3.y, b01.y, acc[7][1]);
            acc[7][2] = fma2(a3.y, b23.x, acc[7][2]);
            acc[7][3] = fma2(a3.y, b23.y, acc[7][3]);
        }
        __syncthreads();
    }

    // ---- epilogue ----
    const int col = n0 + tx * 4;
    float4 bb = make_float4(0.f, 0.f, 0.f, 0.f);
    if (bias) bb = *(const float4*)(bias + col);

#pragma unroll
    for (int p = 0; p < 8; p++) {
        float lo[4], hi[4];
#pragma unroll
        for (int j = 0; j < 4; j++) unpack2(acc[p][j], lo[j], hi[j]);

        int r0 = m0 + ty * 16 + 2 * p;
#pragma unroll
        for (int h = 0; h < 2; h++) {
            int row = r0 + h;
            if (row >= M) continue;
            const float* v = h ? hi : lo;
            float4 r = make_float4(v[0] + bb.x, v[1] + bb.y,
                                   v[2] + bb.z, v[3] + bb.w);
            if (doRelu) {
                r.x = fmaxf(r.x, 0.f); r.y = fmaxf(r.y, 0.f);
                r.z = fmaxf(r.z, 0.f); r.w = fmaxf(r.w, 0.f);
            }
            *(float4*)(C + (size_t)row * N + col) = r;
        }
    }
}

// ---------------- edge bucketing (fixed-capacity CSR-lite + spill) ----------
__global__ void build_buckets(const int* __restrict__ src, const int* __restrict__ dst,
                              int E, int* __restrict__ cnt, int* __restrict__ bucket,
                              int* __restrict__ ovf, int* __restrict__ ovf_cnt)
{
    int e = blockIdx.x * blockDim.x + threadIdx.x;
    if (e >= E) return;
    int d = dst[e];
    int p = atomicAdd(&cnt[d], 1);
    if (p < BCAP) {
        bucket[(size_t)d * BCAP + p] = src[e];
    } else {
        int q = atomicAdd(ovf_cnt, 1);
        if (q < OVFCAP) { ovf[2 * q] = src[e]; ovf[2 * q + 1] = d; }
    }
}

// ---------------------------------------------------------------------------
// Per-dst gather-sum, 4 dst per block, 64 threads per dst, float4 columns:
//   agg[d, 4c..4c+3] = sum_{s in bucket[d]} h[s, 4c..4c+3]
// Warp-level: 32 lanes x 16B = 512B contiguous per LDG.128 burst.
// ---------------------------------------------------------------------------
__global__ __launch_bounds__(256) void aggregate(
    const float* __restrict__ h, const int* __restrict__ cnt,
    const int* __restrict__ bucket, float* __restrict__ agg, int num_dst)
{
    const int g  = threadIdx.x >> 6;          // dst group 0..3 within block
    const int c4 = threadIdx.x & 63;          // float4 column group 0..63
    const int d  = blockIdx.x * 4 + g;
    if (d >= num_dst) return;

    __shared__ int sl[4][BCAP];

    int deg = cnt[d];
    if (deg > BCAP) deg = BCAP;
    if (c4 < deg) sl[g][c4] = bucket[(size_t)d * BCAP + c4];
    __syncthreads();

    float4 a0 = make_float4(0.f, 0.f, 0.f, 0.f);
    float4 a1 = make_float4(0.f, 0.f, 0.f, 0.f);
    float4 a2 = make_float4(0.f, 0.f, 0.f, 0.f);
    float4 a3 = make_float4(0.f, 0.f, 0.f, 0.f);
    int i = 0;
    for (; i + 4 <= deg; i += 4) {
        float4 v0 = *(const float4*)(h + (size_t)sl[g][i + 0] * 256 + c4 * 4);
        float4 v1 = *(const float4*)(h + (size_t)sl[g][i + 1] * 256 + c4 * 4);
        float4 v2 = *(const float4*)(h + (size_t)sl[g][i + 2] * 256 + c4 * 4);
        float4 v3 = *(const float4*)(h + (size_t)sl[g][i + 3] * 256 + c4 * 4);
        a0.x += v0.x; a0.y += v0.y; a0.z += v0.z; a0.w += v0.w;
        a1.x += v1.x; a1.y += v1.y; a1.z += v1.z; a1.w += v1.w;
        a2.x += v2.x; a2.y += v2.y; a2.z += v2.z; a2.w += v2.w;
        a3.x += v3.x; a3.y += v3.y; a3.z += v3.z; a3.w += v3.w;
    }
    for (; i < deg; i++) {
        float4 v = *(const float4*)(h + (size_t)sl[g][i] * 256 + c4 * 4);
        a0.x += v.x; a0.y += v.y; a0.z += v.z; a0.w += v.w;
    }
    float4 r;
    r.x = (a0.x + a1.x) + (a2.x + a3.x);
    r.y = (a0.y + a1.y) + (a2.y + a3.y);
    r.z = (a0.z + a1.z) + (a2.z + a3.z);
    r.w = (a0.w + a1.w) + (a2.w + a3.w);
    *(float4*)(agg + (size_t)d * 256 + c4 * 4) = r;
}

// ---------- overflow cleanup: atomically add spilled edges (normally empty) -
__global__ __launch_bounds__(256) void apply_overflow(
    const float* __restrict__ h, const int* __restrict__ ovf,
    const int* __restrict__ ovf_cnt, float* __restrict__ agg)
{
    int n = *ovf_cnt;
    if (n > OVFCAP) n = OVFCAP;
    int i = blockIdx.x;
    if (i >= n) return;
    int s = ovf[2 * i], d = ovf[2 * i + 1];
    atomicAdd(&agg[(size_t)d * 256 + threadIdx.x],
              h[(size_t)s * 256 + threadIdx.x]);
}

// ------------ prediction: gather pair features (float4 columns) -------------
__global__ __launch_bounds__(64) void gather_mul(
    const float* __restrict__ h,
    const int* __restrict__ ps, const int* __restrict__ pd,
    const int* __restrict__ ns, const int* __restrict__ nd,
    float* __restrict__ e)
{
    int i = blockIdx.x;
    int c4 = threadIdx.x;               // 0..63 float4 groups
    int s, d;
    if (i < NPAIR) { s = ps[i]; d = pd[i]; }
    else           { s = ns[i - NPAIR]; d = nd[i - NPAIR]; }
    float4 a = *(const float4*)(h + (size_t)s * 256 + c4 * 4);
    float4 b = *(const float4*)(h + (size_t)d * 256 + c4 * 4);
    float4 r = make_float4(a.x * b.x, a.y * b.y, a.z * b.z, a.w * b.w);
    *(float4*)(e + (size_t)i * 256 + c4 * 4) = r;
}

// ---------------- prediction: final dot with pw2 ----------------------------
__global__ __launch_bounds__(128) void out_dot(
    const float* __restrict__ hidden, const float* __restrict__ pw2,
    const float* __restrict__ pb2, float* __restrict__ out)
{
    int row = blockIdx.x * 4 + (threadIdx.x >> 5);
    int l = threadIdx.x & 31;
    if (row >= 2 * NPAIR) return;
    float4 hv = ((const float4*)(hidden + (size_t)row * 128))[l];
    float4 wv = ((const float4*)pw2)[l];
    float s = hv.x * wv.x + hv.y * wv.y + hv.z * wv.z + hv.w * wv.w;
#pragma unroll
    for (int off = 16; off > 0; off >>= 1)
        s += __shfl_xor_sync(0xffffffffu, s, off);
    if (l == 0) out[row] = s + pb2[0];
}

// ---------------- launch ----------------------------------------------------
extern "C" void kernel_launch(void* const* d_in, const int* in_sizes, int n_in,
                              void* d_out, int out_size)
{
    const float* x     = (const float*)d_in[0];
    const int*  src0   = (const int*)d_in[1];
    const int*  dst0   = (const int*)d_in[2];
    const int*  src1   = (const int*)d_in[3];
    const int*  dst1   = (const int*)d_in[4];
    const int*  pos_s  = (const int*)d_in[5];
    const int*  pos_d  = (const int*)d_in[6];
    const int*  neg_s  = (const int*)d_in[7];
    const int*  neg_d  = (const int*)d_in[8];
    const float* W0    = (const float*)d_in[9];
    const float* loop0 = (const float*)d_in[10];
    const float* b0    = (const float*)d_in[11];
    const float* W1    = (const float*)d_in[12];
    const float* loop1 = (const float*)d_in[13];
    const float* b1    = (const float*)d_in[14];
    const float* pw1   = (const float*)d_in[15];
    const float* pb1   = (const float*)d_in[16];
    const float* pw2   = (const float*)d_in[17];
    const float* pb2   = (const float*)d_in[18];

    const int E0 = in_sizes[1];
    const int E1 = in_sizes[3];

    float *aggX0, *h1, *aggX1, *ebuf, *hid;
    int *cnt0, *cnt1, *bk0, *bk1, *ovf0, *ovf1;
    cudaGetSymbolAddress((void**)&aggX0, g_aggX0);
    cudaGetSymbolAddress((void**)&h1,    g_h1);
    cudaGetSymbolAddress((void**)&aggX1, g_aggX1);
    cudaGetSymbolAddress((void**)&ebuf,  g_e);
    cudaGetSymbolAddress((void**)&hid,   g_hid);
    cudaGetSymbolAddress((void**)&cnt0,  g_cnt0);
    cudaGetSymbolAddress((void**)&cnt1,  g_cnt1);
    cudaGetSymbolAddress((void**)&bk0,   g_bk0);
    cudaGetSymbolAddress((void**)&bk1,   g_bk1);
    cudaGetSymbolAddress((void**)&ovf0,  g_ovf0);
    cudaGetSymbolAddress((void**)&ovf1,  g_ovf1);

    float* out = (float*)d_out;
    float* h2  = out + 2 * NPAIR;   // h output region [10000, 256]

    cudaMemsetAsync(cnt0, 0, (N_DST0 + 1) * sizeof(int));
    cudaMemsetAsync(cnt1, 0, (N_DST1 + 1) * sizeof(int));

    // ---- layer 0: aggregate x (linearity), then fused bdd+loop GEMM ----
    build_buckets<<<(E0 + 255) / 256, 256>>>(src0, dst0, E0, cnt0, bk0,
                                             ovf0, cnt0 + N_DST0);
    aggregate<<<(N_DST0 + 3) / 4, 256>>>(x, cnt0, bk0, aggX0, N_DST0);
    apply_overflow<<<OVFCAP, 256>>>(x, ovf0, cnt0 + N_DST0, aggX0);
    gemm_fused<<<dim3(4, (N_DST0 + 255) / 256), 256>>>(
        x, loop0, aggX0, W0, b0, h1, N_DST0, 256, 1);

    // ---- layer 1 ----
    build_buckets<<<(E1 + 255) / 256, 256>>>(src1, dst1, E1, cnt1, bk1,
                                             ovf1, cnt1 + N_DST1);
    aggregate<<<(N_DST1 + 3) / 4, 256>>>(h1, cnt1, bk1, aggX1, N_DST1);
    apply_overflow<<<OVFCAP, 256>>>(h1, ovf1, cnt1 + N_DST1, aggX1);
    gemm_fused<<<dim3(4, (N_DST1 + 255) / 256), 256>>>(
        h1, loop1, aggX1, W1, b1, h2, N_DST1, 256, 1);

    // ---- prediction head ----
    gather_mul<<<2 * NPAIR, 64>>>(h2, pos_s, pos_d, neg_s, neg_d, ebuf);
    gemm_fused<<<dim3(2, (2 * NPAIR + 255) / 256), 256>>>(
        ebuf, pw1, nullptr, nullptr, pb1, hid, 2 * NPAIR, 128, 1);
    out_dot<<<(2 * NPAIR + 3) / 4, 128>>>(hid, pw2, pb2, out);
}

// round 12
// speedup vs baseline: 1.1386x; 1.1386x over previous
#include <cuda_runtime.h>
#include <cstdint>

// ---------------- problem constants ----------------
#define N_SRC0 200000
#define N_DST0 50000
#define N_DST1 10000
#define NPAIR  5000
#define FEAT   256
#define NB     4
#define BCAP   64     // Poisson(16); P(deg>64) astronomically small
#define OVFCAP 2048   // spill list for pathological degrees

// ---------------- scratch (static device globals; no runtime alloc) --------
__device__ float g_aggX0[(size_t)N_DST0 * FEAT];  // segment-sum of x rows
__device__ float g_h1[(size_t)N_DST0 * FEAT];
__device__ float g_aggX1[(size_t)N_DST1 * FEAT];
__device__ float g_e[(size_t)(2 * NPAIR) * FEAT];
__device__ float g_hid[(size_t)(2 * NPAIR) * 128];
__device__ int   g_cnt0[N_DST0 + 1];              // last slot = overflow count
__device__ int   g_cnt1[N_DST1 + 1];
__device__ int   g_bk0[(size_t)N_DST0 * BCAP];
__device__ int   g_bk1[(size_t)N_DST1 * BCAP];
__device__ int   g_ovf0[OVFCAP * 2];              // (src,dst) pairs
__device__ int   g_ovf1[OVFCAP * 2];

// ---------------- f32x2 helpers (Blackwell packed FMA) ----------------------
__device__ __forceinline__ unsigned long long fma2(
    unsigned long long a, unsigned long long b, unsigned long long c)
{
    unsigned long long d;
    asm("fma.rn.f32x2 %0, %1, %2, %3;" : "=l"(d) : "l"(a), "l"(b), "l"(c));
    return d;
}
__device__ __forceinline__ unsigned long long dup2(float v)
{
    unsigned long long d;
    asm("mov.b64 %0, {%1, %1};" : "=l"(d) : "f"(v));
    return d;
}
__device__ __forceinline__ void unpack2(unsigned long long p, float& lo, float& hi)
{
    lo = __uint_as_float((unsigned)p);
    hi = __uint_as_float((unsigned)(p >> 32));
}

// ---------------------------------------------------------------------------
// Fused relational-layer GEMM:
//   C[:, n0:n0+64] = relu?( A@B[:, n0:n0+64] + AGG[:, b*64:+64] @ Wb + bias )
// b = blockIdx.x (one bdd base per 64-wide n-tile). AGG==nullptr skips fusion.
// 512 threads/CTA (16 warps/SM => 4/SMSP for latency hiding; R8/R9 showed
// 8 warps/SM left issue at 34%), 256x64 tile, 8x4 microtile with packed
// fma.rn.f32x2, PLAIN f32 B in smem (dup2 to f32x2 on the idle ALU pipe),
// double-buffered smem (one bar per k-tile; staging overlaps compute),
// LDG prefetch 1.5 tiles ahead. Regs ~96 < 128 cap (1 CTA x 512 thr).
// grid = (N/64, ceil(M/256)): n-tiles fastest -> L2 reuse of the A tile.
// ---------------------------------------------------------------------------
__global__ __launch_bounds__(512, 1) void gemm_fused(
    const float* __restrict__ A, const float* __restrict__ B,
    const float* __restrict__ AGG, const float* __restrict__ W,
    const float* __restrict__ bias, float* __restrict__ C,
    int M, int N, int doRelu)
{
    __shared__ __align__(16) float As[2][16][256];   // 2 x 16 KB
    __shared__ __align__(16) float Bs[2][16][64];    // 2 x 4 KB  (40 KB)

    const int tid = threadIdx.x;
    const int n0 = blockIdx.x * 64;
    const int m0 = blockIdx.y * 256;
    const int b  = blockIdx.x;          // bdd base when AGG active (N==256)

    const int ty = tid >> 4;            // 0..31 -> rows ty*8..+7
    const int tx = tid & 15;            // 0..15 -> cols tx*4..+3

    // A staging: 16k x 256 rows; 512 threads, 8 floats (2 float4) each
    const int ar  = tid >> 1;           // 0..255 (row staged by this thread)
    const int akc = (tid & 1) * 8;      // k offset 0 or 8
    // B staging: 16k x 64 cols; threads 0..255 only, one float4 each
    const int bk = (tid >> 4) & 15;
    const int bt = tid & 15;
    const bool bstage = (tid < 256);

    unsigned long long acc[4][4];       // [row-pair][col]
#pragma unroll
    for (int p = 0; p < 4; p++)
#pragma unroll
        for (int j = 0; j < 4; j++) acc[p][j] = 0ull;

    const int arow = m0 + ar;
    const bool aok = (arow < M);
    const float* Wb = W ? (W + (size_t)b * 64 * 64) : nullptr;
    const int ktot = AGG ? 320 : 256;   // 256 main + 64 fused bdd K-steps

    float4 v0, v1;   // A fragment prefetch (8 regs)
    float4 bv;       // B fragment prefetch (4 regs, threads 0..255 only)

    auto load_tile = [&](int kt) {
        v0 = v1 = make_float4(0.f, 0.f, 0.f, 0.f);
        if (aok) {
            const float* src = (kt < 256)
                ? (A + (size_t)arow * 256 + kt + akc)
                : (AGG + (size_t)arow * 256 + b * 64 + (kt - 256) + akc);
            v0 = *(const float4*)(src + 0);
            v1 = *(const float4*)(src + 4);
        }
        if (bstage) {
            if (kt < 256)
                bv = *(const float4*)(B + (size_t)(kt + bk) * N + n0 + bt * 4);
            else
                bv = *(const float4*)(Wb + (size_t)(kt - 256 + bk) * 64 + bt * 4);
        }
    };
    auto stage_tile = [&](int buf) {
        As[buf][akc + 0][ar] = v0.x; As[buf][akc + 1][ar] = v0.y;
        As[buf][akc + 2][ar] = v0.z; As[buf][akc + 3][ar] = v0.w;
        As[buf][akc + 4][ar] = v1.x; As[buf][akc + 5][ar] = v1.y;
        As[buf][akc + 6][ar] = v1.z; As[buf][akc + 7][ar] = v1.w;
        if (bstage) *(float4*)&Bs[buf][bk][bt * 4] = bv;
    };

    // ---- prologue: tile 0 staged to buf 0; tile 1 prefetched ----
    load_tile(0);
    stage_tile(0);
    if (16 < ktot) load_tile(16);
    __syncthreads();

    for (int kt = 0; kt < ktot; kt += 16) {
        const int p = (kt >> 4) & 1;

        // ---- stage next tile into other buffer; prefetch tile+2 ----
        if (kt + 16 < ktot) {
            stage_tile(p ^ 1);
            if (kt + 32 < ktot) load_tile(kt + 32);
        }

        // ---- compute 16 k-steps from buf p ----
#pragma unroll
        for (int k = 0; k < 16; k++) {
            float4 bf = *(const float4*)&Bs[p][k][tx * 4];
            unsigned long long b0 = dup2(bf.x), b1 = dup2(bf.y);
            unsigned long long b2 = dup2(bf.z), b3 = dup2(bf.w);

            ulonglong2 a01 = *(const ulonglong2*)&As[p][k][ty * 8 + 0];
            acc[0][0] = fma2(a01.x, b0, acc[0][0]);
            acc[0][1] = fma2(a01.x, b1, acc[0][1]);
            acc[0][2] = fma2(a01.x, b2, acc[0][2]);
            acc[0][3] = fma2(a01.x, b3, acc[0][3]);
            acc[1][0] = fma2(a01.y, b0, acc[1][0]);
            acc[1][1] = fma2(a01.y, b1, acc[1][1]);
            acc[1][2] = fma2(a01.y, b2, acc[1][2]);
            acc[1][3] = fma2(a01.y, b3, acc[1][3]);

            ulonglong2 a23 = *(const ulonglong2*)&As[p][k][ty * 8 + 4];
            acc[2][0] = fma2(a23.x, b0, acc[2][0]);
            acc[2][1] = fma2(a23.x, b1, acc[2][1]);
            acc[2][2] = fma2(a23.x, b2, acc[2][2]);
            acc[2][3] = fma2(a23.x, b3, acc[2][3]);
            acc[3][0] = fma2(a23.y, b0, acc[3][0]);
            acc[3][1] = fma2(a23.y, b1, acc[3][1]);
            acc[3][2] = fma2(a23.y, b2, acc[3][2]);
            acc[3][3] = fma2(a23.y, b3, acc[3][3]);
        }
        __syncthreads();
    }

    // ---- epilogue ----
    const int col = n0 + tx * 4;
    float4 bb = make_float4(0.f, 0.f, 0.f, 0.f);
    if (bias) bb = *(const float4*)(bias + col);

#pragma unroll
    for (int p = 0; p < 4; p++) {
        float lo[4], hi[4];
#pragma unroll
        for (int j = 0; j < 4; j++) unpack2(acc[p][j], lo[j], hi[j]);

        int r0 = m0 + ty * 8 + 2 * p;
#pragma unroll
        for (int h = 0; h < 2; h++) {
            int row = r0 + h;
            if (row >= M) continue;
            const float* v = h ? hi : lo;
            float4 r = make_float4(v[0] + bb.x, v[1] + bb.y,
                                   v[2] + bb.z, v[3] + bb.w);
            if (doRelu) {
                r.x = fmaxf(r.x, 0.f); r.y = fmaxf(r.y, 0.f);
                r.z = fmaxf(r.z, 0.f); r.w = fmaxf(r.w, 0.f);
            }
            *(float4*)(C + (size_t)row * N + col) = r;
        }
    }
}

// ---------------- edge bucketing (fixed-capacity CSR-lite + spill) ----------
__global__ void build_buckets(const int* __restrict__ src, const int* __restrict__ dst,
                              int E, int* __restrict__ cnt, int* __restrict__ bucket,
                              int* __restrict__ ovf, int* __restrict__ ovf_cnt)
{
    int e = blockIdx.x * blockDim.x + threadIdx.x;
    if (e >= E) return;
    int d = dst[e];
    int p = atomicAdd(&cnt[d], 1);
    if (p < BCAP) {
        bucket[(size_t)d * BCAP + p] = src[e];
    } else {
        int q = atomicAdd(ovf_cnt, 1);
        if (q < OVFCAP) { ovf[2 * q] = src[e]; ovf[2 * q + 1] = d; }
    }
}

// ---------------------------------------------------------------------------
// Per-dst gather-sum, 4 dst per block, 64 threads per dst, float4 columns.
// ---------------------------------------------------------------------------
__global__ __launch_bounds__(256) void aggregate(
    const float* __restrict__ h, const int* __restrict__ cnt,
    const int* __restrict__ bucket, float* __restrict__ agg, int num_dst)
{
    const int g  = threadIdx.x >> 6;          // dst group 0..3 within block
    const int c4 = threadIdx.x & 63;          // float4 column group 0..63
    const int d  = blockIdx.x * 4 + g;
    if (d >= num_dst) return;

    __shared__ int sl[4][BCAP];

    int deg = cnt[d];
    if (deg > BCAP) deg = BCAP;
    if (c4 < deg) sl[g][c4] = bucket[(size_t)d * BCAP + c4];
    __syncthreads();

    float4 a0 = make_float4(0.f, 0.f, 0.f, 0.f);
    float4 a1 = make_float4(0.f, 0.f, 0.f, 0.f);
    float4 a2 = make_float4(0.f, 0.f, 0.f, 0.f);
    float4 a3 = make_float4(0.f, 0.f, 0.f, 0.f);
    int i = 0;
    for (; i + 4 <= deg; i += 4) {
        float4 w0 = *(const float4*)(h + (size_t)sl[g][i + 0] * 256 + c4 * 4);
        float4 w1 = *(const float4*)(h + (size_t)sl[g][i + 1] * 256 + c4 * 4);
        float4 w2 = *(const float4*)(h + (size_t)sl[g][i + 2] * 256 + c4 * 4);
        float4 w3 = *(const float4*)(h + (size_t)sl[g][i + 3] * 256 + c4 * 4);
        a0.x += w0.x; a0.y += w0.y; a0.z += w0.z; a0.w += w0.w;
        a1.x += w1.x; a1.y += w1.y; a1.z += w1.z; a1.w += w1.w;
        a2.x += w2.x; a2.y += w2.y; a2.z += w2.z; a2.w += w2.w;
        a3.x += w3.x; a3.y += w3.y; a3.z += w3.z; a3.w += w3.w;
    }
    for (; i < deg; i++) {
        float4 w = *(const float4*)(h + (size_t)sl[g][i] * 256 + c4 * 4);
        a0.x += w.x; a0.y += w.y; a0.z += w.z; a0.w += w.w;
    }
    float4 r;
    r.x = (a0.x + a1.x) + (a2.x + a3.x);
    r.y = (a0.y + a1.y) + (a2.y + a3.y);
    r.z = (a0.z + a1.z) + (a2.z + a3.z);
    r.w = (a0.w + a1.w) + (a2.w + a3.w);
    *(float4*)(agg + (size_t)d * 256 + c4 * 4) = r;
}

// ---------- overflow cleanup: atomically add spilled edges (normally empty) -
__global__ __launch_bounds__(256) void apply_overflow(
    const float* __restrict__ h, const int* __restrict__ ovf,
    const int* __restrict__ ovf_cnt, float* __restrict__ agg)
{
    int n = *ovf_cnt;
    if (n > OVFCAP) n = OVFCAP;
    int i = blockIdx.x;
    if (i >= n) return;
    int s = ovf[2 * i], d = ovf[2 * i + 1];
    atomicAdd(&agg[(size_t)d * 256 + threadIdx.x],
              h[(size_t)s * 256 + threadIdx.x]);
}

// ------------ prediction: gather pair features (float4 columns) -------------
__global__ __launch_bounds__(64) void gather_mul(
    const float* __restrict__ h,
    const int* __restrict__ ps, const int* __restrict__ pd,
    const int* __restrict__ ns, const int* __restrict__ nd,
    float* __restrict__ e)
{
    int i = blockIdx.x;
    int c4 = threadIdx.x;               // 0..63 float4 groups
    int s, d;
    if (i < NPAIR) { s = ps[i]; d = pd[i]; }
    else           { s = ns[i - NPAIR]; d = nd[i - NPAIR]; }
    float4 a = *(const float4*)(h + (size_t)s * 256 + c4 * 4);
    float4 b = *(const float4*)(h + (size_t)d * 256 + c4 * 4);
    float4 r = make_float4(a.x * b.x, a.y * b.y, a.z * b.z, a.w * b.w);
    *(float4*)(e + (size_t)i * 256 + c4 * 4) = r;
}

// ---------------- prediction: final dot with pw2 ----------------------------
__global__ __launch_bounds__(128) void out_dot(
    const float* __restrict__ hidden, const float* __restrict__ pw2,
    const float* __restrict__ pb2, float* __restrict__ out)
{
    int row = blockIdx.x * 4 + (threadIdx.x >> 5);
    int l = threadIdx.x & 31;
    if (row >= 2 * NPAIR) return;
    float4 hv = ((const float4*)(hidden + (size_t)row * 128))[l];
    float4 wv = ((const float4*)pw2)[l];
    float s = hv.x * wv.x + hv.y * wv.y + hv.z * wv.z + hv.w * wv.w;
#pragma unroll
    for (int off = 16; off > 0; off >>= 1)
        s += __shfl_xor_sync(0xffffffffu, s, off);
    if (l == 0) out[row] = s + pb2[0];
}

// ---------------- launch ----------------------------------------------------
extern "C" void kernel_launch(void* const* d_in, const int* in_sizes, int n_in,
                              void* d_out, int out_size)
{
    const float* x     = (const float*)d_in[0];
    const int*  src0   = (const int*)d_in[1];
    const int*  dst0   = (const int*)d_in[2];
    const int*  src1   = (const int*)d_in[3];
    const int*  dst1   = (const int*)d_in[4];
    const int*  pos_s  = (const int*)d_in[5];
    const int*  pos_d  = (const int*)d_in[6];
    const int*  neg_s  = (const int*)d_in[7];
    const int*  neg_d  = (const int*)d_in[8];
    const float* W0    = (const float*)d_in[9];
    const float* loop0 = (const float*)d_in[10];
    const float* b0    = (const float*)d_in[11];
    const float* W1    = (const float*)d_in[12];
    const float* loop1 = (const float*)d_in[13];
    const float* b1    = (const float*)d_in[14];
    const float* pw1   = (const float*)d_in[15];
    const float* pb1   = (const float*)d_in[16];
    const float* pw2   = (const float*)d_in[17];
    const float* pb2   = (const float*)d_in[18];

    const int E0 = in_sizes[1];
    const int E1 = in_sizes[3];

    float *aggX0, *h1, *aggX1, *ebuf, *hid;
    int *cnt0, *cnt1, *bk0, *bk1, *ovf0, *ovf1;
    cudaGetSymbolAddress((void**)&aggX0, g_aggX0);
    cudaGetSymbolAddress((void**)&h1,    g_h1);
    cudaGetSymbolAddress((void**)&aggX1, g_aggX1);
    cudaGetSymbolAddress((void**)&ebuf,  g_e);
    cudaGetSymbolAddress((void**)&hid,   g_hid);
    cudaGetSymbolAddress((void**)&cnt0,  g_cnt0);
    cudaGetSymbolAddress((void**)&cnt1,  g_cnt1);
    cudaGetSymbolAddress((void**)&bk0,   g_bk0);
    cudaGetSymbolAddress((void**)&bk1,   g_bk1);
    cudaGetSymbolAddress((void**)&ovf0,  g_ovf0);
    cudaGetSymbolAddress((void**)&ovf1,  g_ovf1);

    float* out = (float*)d_out;
    float* h2  = out + 2 * NPAIR;   // h output region [10000, 256]

    cudaMemsetAsync(cnt0, 0, (N_DST0 + 1) * sizeof(int));
    cudaMemsetAsync(cnt1, 0, (N_DST1 + 1) * sizeof(int));

    // ---- layer 0: aggregate x (linearity), then fused bdd+loop GEMM ----
    build_buckets<<<(E0 + 255) / 256, 256>>>(src0, dst0, E0, cnt0, bk0,
                                             ovf0, cnt0 + N_DST0);
    aggregate<<<(N_DST0 + 3) / 4, 256>>>(x, cnt0, bk0, aggX0, N_DST0);
    apply_overflow<<<OVFCAP, 256>>>(x, ovf0, cnt0 + N_DST0, aggX0);
    gemm_fused<<<dim3(4, (N_DST0 + 255) / 256), 512>>>(
        x, loop0, aggX0, W0, b0, h1, N_DST0, 256, 1);

    // ---- layer 1 ----
    build_buckets<<<(E1 + 255) / 256, 256>>>(src1, dst1, E1, cnt1, bk1,
                                             ovf1, cnt1 + N_DST1);
    aggregate<<<(N_DST1 + 3) / 4, 256>>>(h1, cnt1, bk1, aggX1, N_DST1);
    apply_overflow<<<OVFCAP, 256>>>(h1, ovf1, cnt1 + N_DST1, aggX1);
    gemm_fused<<<dim3(4, (N_DST1 + 255) / 256), 512>>>(
        h1, loop1, aggX1, W1, b1, h2, N_DST1, 256, 1);

    // ---- prediction head ----
    gather_mul<<<2 * NPAIR, 64>>>(h2, pos_s, pos_d, neg_s, neg_d, ebuf);
    gemm_fused<<<dim3(2, (2 * NPAIR + 255) / 256), 512>>>(
        ebuf, pw1, nullptr, nullptr, pb1, hid, 2 * NPAIR, 128, 1);
    out_dot<<<(2 * NPAIR + 3) / 4, 128>>>(hid, pw2, pb2, out);
}